// round 1
// baseline (speedup 1.0000x reference)
#include <cuda_runtime.h>
#include <cstdint>

#define CIN 3
#define COUT 16
#define HH 32
#define WW 32
#define OH 30
#define OW 30

// ---- f32x2 packed-math helpers (SASS FFMA2 only reachable via PTX) ----
__device__ __forceinline__ unsigned long long pk2(float a, float b) {
    unsigned long long r;
    asm("mov.b64 %0, {%1, %2};" : "=l"(r) : "f"(a), "f"(b));
    return r;
}
__device__ __forceinline__ unsigned long long fma2(unsigned long long a,
                                                   unsigned long long b,
                                                   unsigned long long c) {
    unsigned long long d;
    asm("fma.rn.f32x2 %0, %1, %2, %3;" : "=l"(d) : "l"(a), "l"(b), "l"(c));
    return d;
}
__device__ __forceinline__ void upk2(unsigned long long v, float& a, float& b) {
    asm("mov.b64 {%0, %1}, %2;" : "=f"(a), "=f"(b) : "l"(v));
}

// One block = one image. 8 warps; warp w computes channels (2w, 2w+1) packed
// into one f32x2 accumulator. Lane = output column (lanes 30,31 idle in compute).
// Rolling 3-row input window kept in registers as duplicated f32x2 pairs so the
// inner loop is pure FFMA2.
__global__ void __launch_bounds__(256) conv3x3_hswish_kernel(
    const float* __restrict__ x,
    const float* __restrict__ wgt,
    const float* __restrict__ bias,
    float* __restrict__ out)
{
    __shared__ float s_in[CIN * HH * WW];  // 3072 floats = 12 KB

    const int n   = blockIdx.x;
    const int tid = threadIdx.x;

    // Cooperative, coalesced image load (768 float4 / 256 threads = 3 each)
    {
        const float4* src = reinterpret_cast<const float4*>(x + (size_t)n * (CIN * HH * WW));
        float4* dst = reinterpret_cast<float4*>(s_in);
        #pragma unroll
        for (int i = 0; i < 3; i++) {
            dst[tid + i * 256] = src[tid + i * 256];
        }
    }
    __syncthreads();

    const int warp = tid >> 5;
    const int lane = tid & 31;
    const int c0   = warp * 2;  // channel pair (c0, c0+1)

    // Weights as 27 packed (w_c0, w_c1) pairs; OIHW layout, O-stride = 27.
    unsigned long long wp[27];
    #pragma unroll
    for (int t = 0; t < 27; t++)
        wp[t] = pk2(wgt[c0 * 27 + t], wgt[(c0 + 1) * 27 + t]);
    const unsigned long long bp = pk2(bias[c0], bias[c0 + 1]);

    if (lane >= OW) return;  // no more barriers below; safe to retire

    // Rolling window: win[slot][ci][kx] holds dup-pair {v,v} of
    // s_in[ci][row(slot)][lane+kx]. Each value is reused by 3 output rows.
    unsigned long long win[3][CIN][3];

    #pragma unroll
    for (int r = 0; r < 2; r++)
        #pragma unroll
        for (int ci = 0; ci < CIN; ci++)
            #pragma unroll
            for (int kx = 0; kx < 3; kx++) {
                float v = s_in[ci * HH * WW + r * WW + lane + kx];
                win[r][ci][kx] = pk2(v, v);
            }

    float* out0 = out + ((size_t)n * COUT + c0) * (OH * OW) + lane;

    // Outer loop period-3 so window slot indices are compile-time constants
    // and the window stays fully register-resident.
    #pragma unroll 1
    for (int yb = 0; yb < OH; yb += 3) {
        #pragma unroll
        for (int j = 0; j < 3; j++) {
            const int y    = yb + j;
            const int snew = (j + 2) % 3;
            // bring in input row y+2 (rows 2..31; always in-bounds)
            #pragma unroll
            for (int ci = 0; ci < CIN; ci++)
                #pragma unroll
                for (int kx = 0; kx < 3; kx++) {
                    float v = s_in[ci * HH * WW + (y + 2) * WW + lane + kx];
                    win[snew][ci][kx] = pk2(v, v);
                }

            unsigned long long acc = bp;
            #pragma unroll
            for (int ci = 0; ci < CIN; ci++)
                #pragma unroll
                for (int ky = 0; ky < 3; ky++) {
                    const int s = (j + ky) % 3;  // compile-time
                    #pragma unroll
                    for (int kx = 0; kx < 3; kx++)
                        acc = fma2(win[s][ci][kx], wp[ci * 9 + ky * 3 + kx], acc);
                }

            float v0, v1;
            upk2(acc, v0, v1);
            // relu(v) * min(v+3, 6) / 6
            float o0 = fmaxf(v0, 0.0f) * fminf(v0 + 3.0f, 6.0f) * (1.0f / 6.0f);
            float o1 = fmaxf(v1, 0.0f) * fminf(v1 + 3.0f, 6.0f) * (1.0f / 6.0f);
            out0[y * OW]           = o0;   // channel c0
            out0[OH * OW + y * OW] = o1;   // channel c0+1
        }
    }
}

extern "C" void kernel_launch(void* const* d_in, const int* in_sizes, int n_in,
                              void* d_out, int out_size) {
    const float* x = (const float*)d_in[0];
    const float* w = (const float*)d_in[1];
    const float* b = (const float*)d_in[2];
    float* out = (float*)d_out;

    const int N = in_sizes[0] / (CIN * HH * WW);  // 4096
    conv3x3_hswish_kernel<<<N, 256>>>(x, w, b, out);
}